// round 6
// baseline (speedup 1.0000x reference)
#include <cuda_runtime.h>
#include <cuda_fp16.h>

#define NU 200000
#define NI 100000
#define NN 300000
#define NE 1000000
#define NE2 2000000
#define SCAN_B 1024
#define NBLK ((NN + SCAN_B - 1) / SCAN_B)   // 293

// Scratch (device globals — no allocation allowed)
__device__ int    g_deg[NN];
__device__ int    g_rowptr[NN + 1];
__device__ int    g_cursor[NN];
__device__ int    g_adj[NE2];
__device__ float  g_dinv[NN];
__device__ float2 g_hA[NN * 16];   // fp16 table: row = 16 x float2 (4 halves) = 128B
__device__ float2 g_hB[NN * 16];
__device__ int    g_part[SCAN_B];

__global__ void k_count(const int* __restrict__ uid, const int* __restrict__ iid) {
    int e = blockIdx.x * blockDim.x + threadIdx.x;
    if (e < NE) {
        atomicAdd(&g_deg[uid[e]], 1);
        atomicAdd(&g_deg[NU + iid[e]], 1);
    }
}

__device__ __forceinline__ float2 pack_half4(float a, float b, float c, float d) {
    __half2 h0 = __floats2half2_rn(a, b);
    __half2 h1 = __floats2half2_rn(c, d);
    float2 r;
    r.x = __uint_as_float(*reinterpret_cast<unsigned int*>(&h0));
    r.y = __uint_as_float(*reinterpret_cast<unsigned int*>(&h1));
    return r;
}

// Block-local scan of degrees -> local-exclusive rowptr; block totals to g_part.
__global__ void k_scan1() {
    __shared__ int s[SCAN_B];
    int i = blockIdx.x * SCAN_B + threadIdx.x;
    int v = (i < NN) ? g_deg[i] : 0;
    s[threadIdx.x] = v;
    __syncthreads();
    for (int off = 1; off < SCAN_B; off <<= 1) {
        int t = (threadIdx.x >= off) ? s[threadIdx.x - off] : 0;
        __syncthreads();
        s[threadIdx.x] += t;
        __syncthreads();
    }
    if (i < NN) g_rowptr[i] = s[threadIdx.x] - v;
    if (threadIdx.x == SCAN_B - 1) g_part[blockIdx.x] = s[SCAN_B - 1];
}

// Every block redundantly scans the 293 partials, finalizes rowptr/cursor/dinv,
// then inits its slice of the fp16 P0 table (P0 = dinv * e0).
__global__ void k_scan23(const float4* __restrict__ ue, const float4* __restrict__ ie) {
    __shared__ int s[SCAN_B];
    int tid = threadIdx.x, b = blockIdx.x;
    int pv = (tid < NBLK) ? g_part[tid] : 0;
    s[tid] = pv;
    __syncthreads();
    for (int off = 1; off < SCAN_B; off <<= 1) {
        int t = (tid >= off) ? s[tid - off] : 0;
        __syncthreads();
        s[tid] += t;
        __syncthreads();
    }
    int boff = (b > 0) ? s[b - 1] : 0;
    int i = b * SCAN_B + tid;
    if (i < NN) {
        int r = g_rowptr[i] + boff;
        g_rowptr[i] = r;
        g_cursor[i] = r;
        int d = g_deg[i];
        g_dinv[i] = (d > 0) ? rsqrtf((float)d) : 0.0f;
    }
    if (i == 0) g_rowptr[NN] = NE2;
    __syncthreads();
    // Init P0 for this block's 1024 nodes (16 float4 each).
    int base = b * (SCAN_B * 16);
    for (int t = tid; t < SCAN_B * 16; t += SCAN_B) {
        int elem = base + t;
        if (elem < NN * 16) {
            float4 x = (elem < NU * 16) ? __ldg(&ue[elem]) : __ldg(&ie[elem - NU * 16]);
            float di = g_dinv[elem >> 4];
            g_hA[elem] = pack_half4(di * x.x, di * x.y, di * x.z, di * x.w);
        }
    }
}

__global__ void k_fill(const int* __restrict__ uid, const int* __restrict__ iid) {
    int e = blockIdx.x * blockDim.x + threadIdx.x;
    if (e < NE) {
        int u  = uid[e];
        int it = NU + iid[e];
        g_adj[atomicAdd(&g_cursor[u], 1)]  = it;
        g_adj[atomicAdd(&g_cursor[it], 1)] = u;
    }
}

// Half-warp (16 lanes) per node; fp16 source rows (128B, one L2 line per neighbor).
// MODE 1: write next, out = 0.25*(e0_input + wd*sum)   (no out read)
// MODE 2: write next, out += 0.25*wd*sum               (ldcs/stcs RMW)
// MODE 3: out += 0.25*wd*sum only
template <int SRC /*0:A->B 1:B->A*/, int MODE>
__global__ void __launch_bounds__(256) k_gather(float4* __restrict__ out,
                                                const float4* __restrict__ ue,
                                                const float4* __restrict__ ie) {
    int gt   = blockIdx.x * blockDim.x + threadIdx.x;
    int node = gt >> 4;
    if (node >= NN) return;
    int lane = gt & 15;

    const float2* __restrict__ sv = (SRC == 0) ? g_hA : g_hB;
    float2*       __restrict__ nv = (SRC == 0) ? g_hB : g_hA;

    int beg = g_rowptr[node];
    int end = g_rowptr[node + 1];

    float ax = 0.f, ay = 0.f, az = 0.f, aw = 0.f;
    for (int base = beg; base < end; base += 16) {
        int idx  = base + lane;
        int myid = (idx < end) ? g_adj[idx] : 0;
        int cnt  = min(16, end - base);
        #pragma unroll 8
        for (int k = 0; k < cnt; k++) {
            int s = __shfl_sync(0xffffffffu, myid, k, 16);
            float2 raw = __ldg(&sv[s * 16 + lane]);
            unsigned u0 = __float_as_uint(raw.x);
            unsigned u1 = __float_as_uint(raw.y);
            float2 f0 = __half22float2(*reinterpret_cast<__half2*>(&u0));
            float2 f1 = __half22float2(*reinterpret_cast<__half2*>(&u1));
            ax += f0.x; ay += f0.y; az += f1.x; aw += f1.y;
        }
    }

    float wd  = g_dinv[node];
    int   off = node * 16 + lane;
    if (MODE == 1 || MODE == 2) {
        float w2 = wd * wd;
        nv[off] = pack_half4(w2 * ax, w2 * ay, w2 * az, w2 * aw);
    }
    float q = 0.25f * wd;
    if (MODE == 1) {
        float4 e0 = (node < NU) ? __ldg(&ue[off]) : __ldg(&ie[off - NU * 16]);
        __stcs(&out[off], make_float4(0.25f * e0.x + q * ax, 0.25f * e0.y + q * ay,
                                      0.25f * e0.z + q * az, 0.25f * e0.w + q * aw));
    } else {
        float4 o = __ldcs(&out[off]);
        o.x += q * ax; o.y += q * ay; o.z += q * az; o.w += q * aw;
        __stcs(&out[off], o);
    }
}

extern "C" void kernel_launch(void* const* d_in, const int* in_sizes, int n_in,
                              void* d_out, int out_size) {
    const float4* ue  = (const float4*)d_in[0];   // user_emb [200000,64]
    const float4* ie  = (const float4*)d_in[1];   // item_emb [100000,64]
    const int*    uid = (const int*)d_in[2];      // user_ids [1M]
    const int*    iid = (const int*)d_in[3];      // item_ids [1M]
    float4*       out = (float4*)d_out;           // [300000,64]

    const int T = 256;

    void* deg_ptr = nullptr;
    cudaGetSymbolAddress(&deg_ptr, g_deg);
    cudaMemsetAsync(deg_ptr, 0, NN * sizeof(int));

    k_count <<<(NE + T - 1) / T, T>>>(uid, iid);
    k_scan1 <<<NBLK, SCAN_B>>>();
    k_scan23<<<NBLK, SCAN_B>>>(ue, ie);
    k_fill  <<<(NE + T - 1) / T, T>>>(uid, iid);

    dim3 g((NN * 16 + T - 1) / T);
    k_gather<0, 1><<<g, T>>>(out, ue, ie);   // layer 1: A -> B, out = 0.25*(e0+e1)
    k_gather<1, 2><<<g, T>>>(out, ue, ie);   // layer 2: B -> A, out += 0.25*e2
    k_gather<0, 3><<<g, T>>>(out, ue, ie);   // layer 3: A only, out += 0.25*e3
}

// round 7
// speedup vs baseline: 1.2586x; 1.2586x over previous
#include <cuda_runtime.h>

#define NU 200000
#define NI 100000
#define NN 300000
#define NE 1000000
#define NE2 2000000
#define SCAN_B 1024
#define NBLK ((NN + SCAN_B - 1) / SCAN_B)   // 293

// Scratch (device globals — no allocation allowed)
__device__ int      g_deg[NN];
__device__ int      g_rowptr[NN + 1];
__device__ int      g_cursor[NN];
__device__ int      g_adj[NE2];
__device__ float    g_dinv[NN];
__device__ float4   g_embA[NN * 16];   // P_L = dinv * e_L, f32, row = 256B
__device__ float4   g_embB[NN * 16];
__device__ int      g_part[SCAN_B];

__global__ void k_count(const int* __restrict__ uid, const int* __restrict__ iid) {
    int e = blockIdx.x * blockDim.x + threadIdx.x;
    if (e < NE) {
        atomicAdd(&g_deg[uid[e]], 1);
        atomicAdd(&g_deg[NU + iid[e]], 1);
    }
}

// Block-local scan of degrees -> local-exclusive rowptr; block totals to g_part.
__global__ void k_scan1() {
    __shared__ int s[SCAN_B];
    int i = blockIdx.x * SCAN_B + threadIdx.x;
    int v = (i < NN) ? g_deg[i] : 0;
    s[threadIdx.x] = v;
    __syncthreads();
    for (int off = 1; off < SCAN_B; off <<= 1) {
        int t = (threadIdx.x >= off) ? s[threadIdx.x - off] : 0;
        __syncthreads();
        s[threadIdx.x] += t;
        __syncthreads();
    }
    if (i < NN) g_rowptr[i] = s[threadIdx.x] - v;
    if (threadIdx.x == SCAN_B - 1) g_part[blockIdx.x] = s[SCAN_B - 1];
}

// Every block redundantly scans the 293 partials, finalizes rowptr/cursor/dinv,
// then inits its slice of the f32 P0 table (P0 = dinv * e0).
__global__ void k_scan23(const float4* __restrict__ ue, const float4* __restrict__ ie) {
    __shared__ int s[SCAN_B];
    int tid = threadIdx.x, b = blockIdx.x;
    int pv = (tid < NBLK) ? g_part[tid] : 0;
    s[tid] = pv;
    __syncthreads();
    for (int off = 1; off < SCAN_B; off <<= 1) {
        int t = (tid >= off) ? s[tid - off] : 0;
        __syncthreads();
        s[tid] += t;
        __syncthreads();
    }
    int boff = (b > 0) ? s[b - 1] : 0;
    int i = b * SCAN_B + tid;
    if (i < NN) {
        int r = g_rowptr[i] + boff;
        g_rowptr[i] = r;
        g_cursor[i] = r;
        int d = g_deg[i];
        g_dinv[i] = (d > 0) ? rsqrtf((float)d) : 0.0f;
    }
    if (i == 0) g_rowptr[NN] = NE2;
    __syncthreads();
    int base = b * (SCAN_B * 16);
    for (int t = tid; t < SCAN_B * 16; t += SCAN_B) {
        int elem = base + t;
        if (elem < NN * 16) {
            float4 x = (elem < NU * 16) ? __ldg(&ue[elem]) : __ldg(&ie[elem - NU * 16]);
            float di = g_dinv[elem >> 4];
            g_embA[elem] = make_float4(di * x.x, di * x.y, di * x.z, di * x.w);
        }
    }
}

__global__ void k_fill(const int* __restrict__ uid, const int* __restrict__ iid) {
    int e = blockIdx.x * blockDim.x + threadIdx.x;
    if (e < NE) {
        int u  = uid[e];
        int it = NU + iid[e];
        g_adj[atomicAdd(&g_cursor[u], 1)]  = it;
        g_adj[atomicAdd(&g_cursor[it], 1)] = u;
    }
}

__device__ __forceinline__ void addx2(unsigned long long& acc, unsigned long long v) {
    asm("add.rn.f32x2 %0, %0, %1;" : "+l"(acc) : "l"(v));
}

// Half-warp (16 lanes) per node; f32 rows (256B). Inner loop: SHFL + LDG.128 + 2x add.f32x2.
// MODE 1: write next, out = 0.25*(e0_input + wd*sum)   (no out read)
// MODE 2: write next, out += 0.25*wd*sum               (ldcs/stcs RMW)
// MODE 3: out += 0.25*wd*sum only
template <int SRC /*0:A->B 1:B->A*/, int MODE>
__global__ void __launch_bounds__(256) k_gather(float4* __restrict__ out,
                                                const float4* __restrict__ ue,
                                                const float4* __restrict__ ie) {
    int gt   = blockIdx.x * blockDim.x + threadIdx.x;
    int node = gt >> 4;
    if (node >= NN) return;
    int lane = gt & 15;

    const longlong2* __restrict__ sv =
        (const longlong2*)((SRC == 0) ? g_embA : g_embB);
    float4*           __restrict__ nv = (SRC == 0) ? g_embB : g_embA;

    int beg = __ldg(&g_rowptr[node]);
    int end = __ldg(&g_rowptr[node + 1]);

    unsigned long long a0 = 0ULL, a1 = 0ULL;   // packed {f32,f32} accumulators
    for (int base = beg; base < end; base += 16) {
        int idx  = base + lane;
        int myid = (idx < end) ? __ldg(&g_adj[idx]) : 0;
        int cnt  = min(16, end - base);
        #pragma unroll 8
        for (int k = 0; k < cnt; k++) {
            int s = __shfl_sync(0xffffffffu, myid, k, 16);
            longlong2 v = __ldg(&sv[s * 16 + lane]);
            addx2(a0, (unsigned long long)v.x);
            addx2(a1, (unsigned long long)v.y);
        }
    }

    float ax = __uint_as_float((unsigned)(a0 & 0xFFFFFFFFull));
    float ay = __uint_as_float((unsigned)(a0 >> 32));
    float az = __uint_as_float((unsigned)(a1 & 0xFFFFFFFFull));
    float aw = __uint_as_float((unsigned)(a1 >> 32));

    float wd  = g_dinv[node];
    int   off = node * 16 + lane;
    if (MODE == 1 || MODE == 2) {
        float w2 = wd * wd;
        nv[off] = make_float4(w2 * ax, w2 * ay, w2 * az, w2 * aw);
    }
    float q = 0.25f * wd;
    if (MODE == 1) {
        float4 e0 = (node < NU) ? __ldg(&ue[off]) : __ldg(&ie[off - NU * 16]);
        __stcs(&out[off], make_float4(0.25f * e0.x + q * ax, 0.25f * e0.y + q * ay,
                                      0.25f * e0.z + q * az, 0.25f * e0.w + q * aw));
    } else {
        float4 o = __ldcs(&out[off]);
        o.x += q * ax; o.y += q * ay; o.z += q * az; o.w += q * aw;
        __stcs(&out[off], o);
    }
}

extern "C" void kernel_launch(void* const* d_in, const int* in_sizes, int n_in,
                              void* d_out, int out_size) {
    const float4* ue  = (const float4*)d_in[0];   // user_emb [200000,64]
    const float4* ie  = (const float4*)d_in[1];   // item_emb [100000,64]
    const int*    uid = (const int*)d_in[2];      // user_ids [1M]
    const int*    iid = (const int*)d_in[3];      // item_ids [1M]
    float4*       out = (float4*)d_out;           // [300000,64]

    const int T = 256;

    void* deg_ptr = nullptr;
    cudaGetSymbolAddress(&deg_ptr, g_deg);
    cudaMemsetAsync(deg_ptr, 0, NN * sizeof(int));

    k_count <<<(NE + T - 1) / T, T>>>(uid, iid);
    k_scan1 <<<NBLK, SCAN_B>>>();
    k_scan23<<<NBLK, SCAN_B>>>(ue, ie);
    k_fill  <<<(NE + T - 1) / T, T>>>(uid, iid);

    dim3 g((NN * 16 + T - 1) / T);
    k_gather<0, 1><<<g, T>>>(out, ue, ie);   // layer 1: A -> B, out = 0.25*(e0+e1)
    k_gather<1, 2><<<g, T>>>(out, ue, ie);   // layer 2: B -> A, out += 0.25*e2
    k_gather<0, 3><<<g, T>>>(out, ue, ie);   // layer 3: A only, out += 0.25*e3
}